// round 9
// baseline (speedup 1.0000x reference)
#include <cuda_runtime.h>
#include <stdint.h>

// Shapes (fixed by the problem)
#define BATCH 32
#define SEQ   4096
#define VOCAB 10
#define FEAT  1024
#define DIM   64

#define CHUNK   256
#define THREADS 256

// Precomputed projected table: P[d][v] = b[d] + sum_f fp[v][f] * W[d][f]
__device__ float g_P[DIM * VOCAB];

// ---------------------------------------------------------------------------
// Kernel 1: 10x64x1024 GEMM, one CTA per d-row (64 CTAs x 320 threads).
// All 10 warps of a CTA read the SAME W row -> one 4KB DRAM stream per CTA,
// 64 concurrent streams, L2 multicast fans it out. Each warp: 16 independent
// LDG.128 -> single DRAM-latency round, then shfl-reduce.
// ---------------------------------------------------------------------------
__global__ void __launch_bounds__(320)
compute_P_kernel(const float* __restrict__ fp,
                 const float* __restrict__ W,
                 const float* __restrict__ bias) {
    const int d    = blockIdx.x;          // 0..63
    const int v    = threadIdx.x >> 5;    // warp id = vocab row (0..9)
    const int lane = threadIdx.x & 31;

    const float4* fr = reinterpret_cast<const float4*>(fp + v * FEAT);
    const float4* wr = reinterpret_cast<const float4*>(W  + d * FEAT);

    float s = 0.f;
#pragma unroll
    for (int f = lane; f < FEAT / 4; f += 32) {   // 8 iters, fully unrolled
        float4 a = fr[f];
        float4 c = wr[f];
        s += a.x * c.x + a.y * c.y + a.z * c.z + a.w * c.w;
    }

#pragma unroll
    for (int o = 16; o > 0; o >>= 1)
        s += __shfl_down_sync(0xffffffffu, s, o);

    if (lane == 0)
        g_P[d * VOCAB + v] = s + bias[d];

    __threadfence();                      // publish g_P
    cudaTriggerProgrammaticLaunchCompletion();
}

// ---------------------------------------------------------------------------
// Kernel 2: gather. out[(b*DIM + d)*SEQ + l] = P[d][idx[b][l]]
// (unchanged from R8 — pinned at the ~3.3 TB/s L2 write-path cap)
// ---------------------------------------------------------------------------
__global__ void __launch_bounds__(THREADS)
gather_kernel(const int* __restrict__ idx, float* __restrict__ out) {
    __shared__ float sP[DIM * VOCAB];

    const int b   = blockIdx.y;
    const int l0  = blockIdx.x * CHUNK;
    const int tid = threadIdx.x;
    const int lq  = tid & 63;            // float4 slot within chunk (fixed)
    const int db  = tid >> 6;            // base d-row (0..3)

    // P-independent prelude: this thread's 4 vocab indices (coalesced 16B)
    int4 iv = *reinterpret_cast<const int4*>(idx + b * SEQ + l0 + lq * 4);

    // HW wait for compute_P_kernel (no spin)
    cudaGridDependencySynchronize();

    // Projected table into shared: [d][v]
    for (int i = tid; i < DIM * VOCAB; i += THREADS)
        sP[i] = g_P[i];
    __syncthreads();

    float* ob = out + (b * DIM) * SEQ + l0 + lq * 4;

#pragma unroll
    for (int k = 0; k < 16; k++) {
        const int d = db + 4 * k;
        const float* p = &sP[d * VOCAB];
        float4 r;
        r.x = p[iv.x];
        r.y = p[iv.y];
        r.z = p[iv.z];
        r.w = p[iv.w];
        *reinterpret_cast<float4*>(ob + d * SEQ) = r;
    }
}

// ---------------------------------------------------------------------------
// Inputs per metadata order: indices (int32), fp_table (f32), W (f32), b (f32)
// ---------------------------------------------------------------------------
extern "C" void kernel_launch(void* const* d_in, const int* in_sizes, int n_in,
                              void* d_out, int out_size) {
    const int*   idx  = (const int*)d_in[0];
    const float* fp   = (const float*)d_in[1];
    const float* W    = (const float*)d_in[2];
    const float* bias = (const float*)d_in[3];
    float*       out  = (float*)d_out;

    // Producer: one CTA per d-row
    compute_P_kernel<<<DIM, 320>>>(fp, W, bias);

    // Consumer: PDL launch
    cudaLaunchConfig_t cfg = {};
    cfg.gridDim          = dim3(SEQ / CHUNK, BATCH);   // (16, 32) = 512 CTAs
    cfg.blockDim         = dim3(THREADS, 1, 1);
    cfg.dynamicSmemBytes = 0;
    cfg.stream           = 0;

    cudaLaunchAttribute attr[1];
    attr[0].id = cudaLaunchAttributeProgrammaticStreamSerialization;
    attr[0].val.programmaticStreamSerializationAllowed = 1;
    cfg.attrs    = attr;
    cfg.numAttrs = 1;

    cudaLaunchKernelEx(&cfg, gather_kernel, idx, out);
}

// round 10
// speedup vs baseline: 1.0326x; 1.0326x over previous
#include <cuda_runtime.h>
#include <stdint.h>

// Shapes (fixed by the problem)
#define BATCH 32
#define SEQ   4096
#define VOCAB 10
#define FEAT  1024
#define DIM   64

#define CHUNK   256
#define THREADS 256

// Precomputed projected table: P[d][v] = b[d] + sum_f fp[v][f] * W[d][f]
__device__ float g_P[DIM * VOCAB];

// ---------------------------------------------------------------------------
// Kernel 1: tiny 10x64x1024 GEMM. One warp per (d, v) pair -> 640 warps.
// ---------------------------------------------------------------------------
__global__ void compute_P_kernel(const float* __restrict__ fp,
                                 const float* __restrict__ W,
                                 const float* __restrict__ bias) {
    int w    = (blockIdx.x * blockDim.x + threadIdx.x) >> 5;
    int lane = threadIdx.x & 31;
    int d = w / VOCAB;
    int v = w - d * VOCAB;

    const float4* fr = reinterpret_cast<const float4*>(fp + v * FEAT);
    const float4* wr = reinterpret_cast<const float4*>(W  + d * FEAT);

    float s = 0.f;
#pragma unroll
    for (int f = lane; f < FEAT / 4; f += 32) {
        float4 a = fr[f];
        float4 c = wr[f];
        s += a.x * c.x + a.y * c.y + a.z * c.z + a.w * c.w;
    }

#pragma unroll
    for (int o = 16; o > 0; o >>= 1)
        s += __shfl_down_sync(0xffffffffu, s, o);

    if (lane == 0)
        g_P[d * VOCAB + v] = s + bias[d];

    __threadfence();
    cudaTriggerProgrammaticLaunchCompletion();
}

// ---------------------------------------------------------------------------
// Kernel 2: gather with 256-bit stores (sm_100+ st.global.v8.f32).
// Thread owns an 8-float slot (lq = tid&31) over 8 d-rows (d = tid>>5 + 8k).
// Same bytes/coalescing as before, HALF the store instructions.
// ---------------------------------------------------------------------------
__global__ void __launch_bounds__(THREADS)
gather_kernel(const int* __restrict__ idx, float* __restrict__ out) {
    __shared__ float sP[DIM * VOCAB];

    const int b   = blockIdx.y;
    const int l0  = blockIdx.x * CHUNK;
    const int tid = threadIdx.x;
    const int lq  = tid & 31;            // 8-float slot within chunk (fixed)
    const int db  = tid >> 5;            // base d-row (0..7)

    // This thread's 8 vocab indices: two coalesced int4 loads
    const int4* ip = reinterpret_cast<const int4*>(idx + b * SEQ + l0 + lq * 8);
    int4 iv0 = ip[0];
    int4 iv1 = ip[1];

    cudaGridDependencySynchronize();

    for (int i = tid; i < DIM * VOCAB; i += THREADS)
        sP[i] = g_P[i];
    __syncthreads();

    float* ob = out + (b * DIM) * SEQ + l0 + lq * 8;

#pragma unroll
    for (int k = 0; k < 8; k++) {
        const int d = db + 8 * k;
        const float* p = &sP[d * VOCAB];

        float r0 = p[iv0.x], r1 = p[iv0.y], r2 = p[iv0.z], r3 = p[iv0.w];
        float r4 = p[iv1.x], r5 = p[iv1.y], r6 = p[iv1.z], r7 = p[iv1.w];

        asm volatile(
            "st.global.v8.f32 [%0], {%1,%2,%3,%4,%5,%6,%7,%8};"
            :: "l"(ob + d * SEQ),
               "f"(r0), "f"(r1), "f"(r2), "f"(r3),
               "f"(r4), "f"(r5), "f"(r6), "f"(r7)
            : "memory");
    }
}

// ---------------------------------------------------------------------------
// Inputs per metadata order: indices (int32), fp_table (f32), W (f32), b (f32)
// ---------------------------------------------------------------------------
extern "C" void kernel_launch(void* const* d_in, const int* in_sizes, int n_in,
                              void* d_out, int out_size) {
    const int*   idx  = (const int*)d_in[0];
    const float* fp   = (const float*)d_in[1];
    const float* W    = (const float*)d_in[2];
    const float* bias = (const float*)d_in[3];
    float*       out  = (float*)d_out;

    compute_P_kernel<<<80, 256>>>(fp, W, bias);

    cudaLaunchConfig_t cfg = {};
    cfg.gridDim          = dim3(SEQ / CHUNK, BATCH);   // (16, 32) = 512 CTAs
    cfg.blockDim         = dim3(THREADS, 1, 1);
    cfg.dynamicSmemBytes = 0;
    cfg.stream           = 0;

    cudaLaunchAttribute attr[1];
    attr[0].id = cudaLaunchAttributeProgrammaticStreamSerialization;
    attr[0].val.programmaticStreamSerializationAllowed = 1;
    cfg.attrs    = attr;
    cfg.numAttrs = 1;

    cudaLaunchKernelEx(&cfg, gather_kernel, idx, out);
}